// round 9
// baseline (speedup 1.0000x reference)
#include <cuda_runtime.h>
#include <cuda_bf16.h>

#define B_      8
#define NVAL    1024
#define MVAL    1024
#define CIN     8
#define CREP    9
#define COUT    16

#define MBLK    8                    // m per block (per warp: lane&7)
#define MT      (MVAL / MBLK)        // 128 m-tiles -> grid = 8*128 = 1024
#define WARPS   8
#define NTHREADS (32 * WARPS)        // 256
#define NWCHUNK (NVAL / WARPS)       // 128 n per warp
#define NITER   (NWCHUNK / 8)        // 16: 8 n per warp-iter (4 subsets x 2)

typedef unsigned long long u64;

__device__ __forceinline__ u64 pack2(float lo, float hi) {
    u64 r; asm("mov.b64 %0, {%1, %2};" : "=l"(r) : "f"(lo), "f"(hi)); return r;
}
__device__ __forceinline__ void unpack2(u64 v, float& lo, float& hi) {
    asm("mov.b64 {%0, %1}, %2;" : "=f"(lo), "=f"(hi) : "l"(v));
}
__device__ __forceinline__ u64 add2(u64 a, u64 b) {
    u64 r; asm("add.rn.f32x2 %0, %1, %2;" : "=l"(r) : "l"(a), "l"(b)); return r;
}
__device__ __forceinline__ u64 mul2(u64 a, u64 b) {
    u64 r; asm("mul.rn.f32x2 %0, %1, %2;" : "=l"(r) : "l"(a), "l"(b)); return r;
}
__device__ __forceinline__ u64 fma2(u64 a, u64 b, u64 c) {
    u64 r; asm("fma.rn.f32x2 %0, %1, %2, %3;" : "=l"(r) : "l"(a), "l"(b), "l"(c)); return r;
}
__device__ __forceinline__ float ex2(float x) {   // MUFU.EX2
    float r; asm("ex2.approx.f32 %0, %1;" : "=f"(r) : "f"(x)); return r;
}

__global__ __launch_bounds__(NTHREADS, 6)
void convcnp_one(const float* __restrict__ gx,
                 const float* __restrict__ gy,
                 const float* __restrict__ gt,
                 const float* __restrict__ gsigma,
                 const float* __restrict__ gW,
                 const float* __restrict__ gbias,
                 float* __restrict__ gout)
{
    // 36KB pool: s_u (4KB, -> red after loop), s_yA (16KB, -> s_tot), s_yB (16KB)
    __shared__ float s_u [NVAL];
    __shared__ float s_yA[NVAL * 4];
    __shared__ float s_yB[NVAL * 4];

    const int b    = blockIdx.x >> 7;          // MT = 128
    const int mt   = blockIdx.x & (MT - 1);
    const int tid  = threadIdx.x;
    const int lane = tid & 31;
    const int w    = tid >> 5;
    const int ml   = lane & (MBLK - 1);        // local m (0-7)
    const int nsub = lane >> 3;                // n-subset (0-3)

    float kk[CREP];
    bool same = true;
    #pragma unroll
    for (int c = 0; c < CREP; c++) {
        float s = __expf(gsigma[c]);
        kk[c] = -0.5f * 1.4426950408889634f / (s * s);
        if (c > 0 && kk[c] != kk[0]) same = false;
    }
    const float sf = same ? sqrtf(-kk[0]) : 1.0f;

    for (int i = tid; i < NVAL; i += NTHREADS)
        s_u[i] = gx[b * NVAL + i] * sf;
    {   // split y: s_yA = ch0-3, s_yB = ch4-7 (16B row stride -> conflict-free LDS.128)
        const float4* y4 = (const float4*)(gy + b * NVAL * CIN);
        float4* a4 = (float4*)s_yA;
        float4* b4 = (float4*)s_yB;
        #pragma unroll
        for (int i = tid; i < NVAL; i += NTHREADS) {
            a4[i] = y4[2 * i];
            b4[i] = y4[2 * i + 1];
        }
    }
    const int   m  = mt * MBLK + ml;
    const float tm = gt[b * MVAL + m] * sf;
    __syncthreads();

    const int n0 = w * NWCHUNK + 2 * nsub;
    float sum[CREP];

    if (same) {
        const u64 nvv  = pack2(-tm, -tm);
        const u64 neg1 = pack2(-1.0f, -1.0f);
        u64 dd0 = 0, A12 = 0, A34 = 0, A56 = 0, A78 = 0;

        #pragma unroll 4
        for (int i = 0; i < NITER; i++) {
            const int n = n0 + 8 * i;
            u64 u2 = *(const u64*)&s_u[n];
            ulonglong2 yA = *(const ulonglong2*)&s_yA[n * 4];
            ulonglong2 yB = *(const ulonglong2*)&s_yB[n * 4];
            ulonglong2 zA = *(const ulonglong2*)&s_yA[(n + 1) * 4];
            ulonglong2 zB = *(const ulonglong2*)&s_yB[(n + 1) * 4];

            u64 a  = add2(u2, nvv);          // (u - v)
            u64 na = mul2(a, neg1);          // -(u - v)
            u64 dq = mul2(a, na);            // -(u - v)^2 (pre-scaled)
            float f0, f1; unpack2(dq, f0, f1);
            float e0 = ex2(f0), e1 = ex2(f1);
            dd0 = add2(dd0, pack2(e0, e1));
            u64 e00 = pack2(e0, e0), e11 = pack2(e1, e1);
            A12 = fma2(e00, yA.x, A12);  A34 = fma2(e00, yA.y, A34);
            A56 = fma2(e00, yB.x, A56);  A78 = fma2(e00, yB.y, A78);
            A12 = fma2(e11, zA.x, A12);  A34 = fma2(e11, zA.y, A34);
            A56 = fma2(e11, zB.x, A56);  A78 = fma2(e11, zB.y, A78);
        }
        // Reduce over the 4 n-subsets (lanes xor 8, xor 16 share the same m).
        dd0 = add2(dd0, __shfl_xor_sync(0xffffffffu, dd0, 8));
        A12 = add2(A12, __shfl_xor_sync(0xffffffffu, A12, 8));
        A34 = add2(A34, __shfl_xor_sync(0xffffffffu, A34, 8));
        A56 = add2(A56, __shfl_xor_sync(0xffffffffu, A56, 8));
        A78 = add2(A78, __shfl_xor_sync(0xffffffffu, A78, 8));
        dd0 = add2(dd0, __shfl_xor_sync(0xffffffffu, dd0, 16));
        A12 = add2(A12, __shfl_xor_sync(0xffffffffu, A12, 16));
        A34 = add2(A34, __shfl_xor_sync(0xffffffffu, A34, 16));
        A56 = add2(A56, __shfl_xor_sync(0xffffffffu, A56, 16));
        A78 = add2(A78, __shfl_xor_sync(0xffffffffu, A78, 16));

        float lo, hi;
        unpack2(dd0, lo, hi);  sum[0] = lo + hi;
        unpack2(A12, sum[1], sum[2]); unpack2(A34, sum[3], sum[4]);
        unpack2(A56, sum[5], sum[6]); unpack2(A78, sum[7], sum[8]);
    } else {
        #pragma unroll
        for (int c = 0; c < CREP; c++) sum[c] = 0.0f;
        for (int i = 0; i < NITER; i++) {
            #pragma unroll
            for (int k = 0; k < 2; k++) {
                const int n = n0 + 8 * i + k;
                float a = s_u[n] - tm, d = a * a;
                const float4 ya = *(const float4*)&s_yA[n * 4];
                const float4 yb = *(const float4*)&s_yB[n * 4];
                sum[0] += ex2(d * kk[0]);
                sum[1] = fmaf(ex2(d * kk[1]), ya.x, sum[1]);
                sum[2] = fmaf(ex2(d * kk[2]), ya.y, sum[2]);
                sum[3] = fmaf(ex2(d * kk[3]), ya.z, sum[3]);
                sum[4] = fmaf(ex2(d * kk[4]), ya.w, sum[4]);
                sum[5] = fmaf(ex2(d * kk[5]), yb.x, sum[5]);
                sum[6] = fmaf(ex2(d * kk[6]), yb.y, sum[6]);
                sum[7] = fmaf(ex2(d * kk[7]), yb.z, sum[7]);
                sum[8] = fmaf(ex2(d * kk[8]), yb.w, sum[8]);
            }
        }
        #pragma unroll
        for (int c = 0; c < CREP; c++) {
            sum[c] += __shfl_xor_sync(0xffffffffu, sum[c], 8);
            sum[c] += __shfl_xor_sync(0xffffffffu, sum[c], 16);
        }
    }

    // Cross-warp reduce in retired s_u space: red[w][ml][c] (576 floats).
    __syncthreads();
    float* red = s_u;
    if (nsub == 0) {
        #pragma unroll
        for (int c = 0; c < CREP; c++)
            red[(w * MBLK + ml) * CREP + c] = sum[c];
    }
    __syncthreads();

    float* s_tot = s_yA;                 // 72 floats in retired yA space
    if (tid < MBLK * CREP) {
        float s = 0.0f;
        #pragma unroll
        for (int ww = 0; ww < WARPS; ww++)
            s += red[ww * (MBLK * CREP) + tid];
        s_tot[tid] = s;
    }
    __syncthreads();

    // GEMV: 128 threads = 8 m x 16 o.
    if (tid < MBLK * COUT) {
        const int mm = tid >> 4;
        const int o  = tid & (COUT - 1);
        const float density = s_tot[mm * CREP];
        const float inv = 1.0f / (density + 1e-8f);
        float r = __ldg(&gbias[o]) + __ldg(&gW[o * CREP]) * density;
        #pragma unroll
        for (int c = 1; c < CREP; c++)
            r = fmaf(__ldg(&gW[o * CREP + c]), s_tot[mm * CREP + c] * inv, r);
        gout[((size_t)b * MVAL + mt * MBLK + mm) * COUT + o] = r;
    }
}

extern "C" void kernel_launch(void* const* d_in, const int* in_sizes, int n_in,
                              void* d_out, int out_size) {
    const float* x     = (const float*)d_in[0];
    const float* y     = (const float*)d_in[1];
    const float* t     = (const float*)d_in[2];
    const float* sigma = (const float*)d_in[3];
    const float* W     = (const float*)d_in[4];
    const float* bias  = (const float*)d_in[5];
    float* out = (float*)d_out;

    convcnp_one<<<B_ * MT, NTHREADS>>>(x, y, t, sigma, W, bias, out);  // 1024 blocks
}